// round 14
// baseline (speedup 1.0000x reference)
#include <cuda_runtime.h>
#include <cuda_fp16.h>
#include <cstdint>
#include <math.h>

#define BB 4
#define TT 2048
#define CC 1024
#define NH 16
#define HD 64
#define M1 (BB*TT)          // 8192
#define N_QKV (3*CC)        // 3072

// q pre-scale: 1/sqrt(64) * log2(e)  -> softmax computed base-2
#define QSCALE 0.180336880111120436f

// ---------------------------------------------------------------------------
// Device-global scratch: pure fp16 operands.  Weights kept K-major [K,N].
// ---------------------------------------------------------------------------
__device__ __half g_xh[M1*CC];
__device__ __half g_wq[CC*N_QKV];     // [K=1024, N=3072] fp16
__device__ __half g_wp[CC*CC];        // [K=1024, N=1024] fp16
__device__ __half g_qh[BB*NH*TT*HD];
__device__ __half g_kh[BB*NH*TT*HD];
__device__ __half g_vh[BB*NH*TT*HD];
__device__ __half g_ah[M1*CC];

// ---------------------------------------------------------------------------
// PTX helpers
// ---------------------------------------------------------------------------
__device__ __forceinline__ uint32_t smem_u32(const void* p) {
    uint32_t a;
    asm("{ .reg .u64 t; cvta.to.shared.u64 t, %1; cvt.u32.u64 %0, t; }"
        : "=r"(a) : "l"(p));
    return a;
}
__device__ __forceinline__ void cpasync16(uint32_t dst, const void* src) {
    asm volatile("cp.async.cg.shared.global [%0], [%1], 16;"
                 :: "r"(dst), "l"(src) : "memory");
}
#define CP_COMMIT() asm volatile("cp.async.commit_group;" ::: "memory")
#define CP_WAIT(N)  asm volatile("cp.async.wait_group %0;" :: "n"(N) : "memory")

__device__ __forceinline__ void ldsm4(uint32_t& r0, uint32_t& r1, uint32_t& r2,
                                      uint32_t& r3, uint32_t a) {
    asm volatile("ldmatrix.sync.aligned.m8n8.x4.shared.b16 {%0,%1,%2,%3},[%4];"
                 : "=r"(r0), "=r"(r1), "=r"(r2), "=r"(r3) : "r"(a));
}
__device__ __forceinline__ void ldsm4t(uint32_t& r0, uint32_t& r1, uint32_t& r2,
                                       uint32_t& r3, uint32_t a) {
    asm volatile("ldmatrix.sync.aligned.m8n8.x4.trans.shared.b16 {%0,%1,%2,%3},[%4];"
                 : "=r"(r0), "=r"(r1), "=r"(r2), "=r"(r3) : "r"(a));
}
__device__ __forceinline__ void ldsm2t(uint32_t& r0, uint32_t& r1, uint32_t a) {
    asm volatile("ldmatrix.sync.aligned.m8n8.x2.trans.shared.b16 {%0,%1},[%2];"
                 : "=r"(r0), "=r"(r1) : "r"(a));
}
__device__ __forceinline__ void mma16816(float* c, const uint32_t* a,
                                         uint32_t b0, uint32_t b1) {
    asm volatile("mma.sync.aligned.m16n8k16.row.col.f32.f16.f16.f32 "
                 "{%0,%1,%2,%3},{%4,%5,%6,%7},{%8,%9},{%0,%1,%2,%3};"
                 : "+f"(c[0]), "+f"(c[1]), "+f"(c[2]), "+f"(c[3])
                 : "r"(a[0]), "r"(a[1]), "r"(a[2]), "r"(a[3]), "r"(b0), "r"(b1));
}

__device__ __forceinline__ void hi_store(__half* dh, size_t off, float v0, float v1) {
    __half2 hp = __halves2half2(__float2half(v0), __float2half(v1));
    *(uint32_t*)(dh + off) = *(uint32_t*)&hp;
}
__device__ __forceinline__ uint32_t pack_h2(float v0, float v1) {
    __half2 hp = __halves2half2(__float2half(v0), __float2half(v1));
    return *(uint32_t*)&hp;
}
__device__ __forceinline__ uint32_t h2ex2(uint32_t x) {
    uint32_t r;
    asm volatile("ex2.approx.f16x2 %0, %1;" : "=r"(r) : "r"(x));
    return r;
}

// ---------------------------------------------------------------------------
// Fused prep: x, w_attn, w_proj fp32 -> fp16 (coalesced, 8B stores)
// ---------------------------------------------------------------------------
#define N_X4  (M1*CC/4)          // 2097152
#define N_WQ4 (CC*N_QKV/4)       // 786432
#define N_WP4 (CC*CC/4)          // 262144
#define PREP_BLOCKS ((N_X4 + N_WQ4 + N_WP4) / 256)   // 12288

__global__ __launch_bounds__(256) void prep_convert(const float* __restrict__ x,
                                                    const float* __restrict__ wa,
                                                    const float* __restrict__ wp)
{
    int i = blockIdx.x * 256 + threadIdx.x;
    const float* src;
    __half* dst;
    if (i < N_X4)               { src = x;  dst = g_xh; }
    else if (i < N_X4 + N_WQ4)  { i -= N_X4;  src = wa; dst = g_wq; }
    else                        { i -= N_X4 + N_WQ4; src = wp; dst = g_wp; }
    float4 v = ((const float4*)src)[i];
    uint2 p;
    p.x = pack_h2(v.x, v.y);
    p.y = pack_h2(v.z, v.w);
    *(uint2*)(dst + (size_t)i * 4) = p;
}

// ---------------------------------------------------------------------------
// GEMM (R11-exact, best measured): C[128x128] = A[M,1024] @ W[1024,N] + bias.
// 256 thr, 8 warps (2x4) 64x32 tiles, BK=64, 3 stages.
// A smem: 128 rows x 144B (ldsm4). B smem: 64 k-rows x 272B (ldsm4t).
// ---------------------------------------------------------------------------
#define GSTA 18432
#define GSTB 17408
#define GST  (GSTA + GSTB)       // 35840
#define GSMEM (3*GST)            // 107520

template<int EPI>
__global__ __launch_bounds__(256, 2) void mma_gemm(const float* __restrict__ bias,
                                                   float* __restrict__ outp)
{
    const __half* Ah = (EPI == 0) ? g_xh : g_ah;
    const __half* Bw = (EPI == 0) ? g_wq : g_wp;
    const int N = (EPI == 0) ? N_QKV : CC;

    extern __shared__ char smc[];
    const uint32_t smb = smem_u32(smc);
    const int t = threadIdx.x, wid = t >> 5, l = t & 31;
    const int wm = wid >> 2, wn = wid & 3;
    const int n0 = blockIdx.x * 128, m0 = blockIdx.y * 128;

    float acc[4][4][4];
    #pragma unroll
    for (int i = 0; i < 4; i++)
        #pragma unroll
        for (int j = 0; j < 4; j++)
            #pragma unroll
            for (int k = 0; k < 4; k++) acc[i][j][k] = 0.f;

    auto issue = [&](int s) {
        const int koff = s * 64;
        const uint32_t sb = smb + (s % 3) * GST;
        #pragma unroll
        for (int i = 0; i < 4; i++) {
            int c = t + i * 256;
            int row = c >> 3, q = c & 7;
            cpasync16(sb + (uint32_t)(row * 144 + q * 16),
                      Ah + (size_t)(m0 + row) * CC + koff + q * 8);
        }
        #pragma unroll
        for (int i = 0; i < 4; i++) {
            int c = t + i * 256;
            int row = c >> 4, q = c & 15;
            cpasync16(sb + GSTA + (uint32_t)(row * 272 + q * 16),
                      Bw + (size_t)(koff + row) * N + n0 + q * 8);
        }
        CP_COMMIT();
    };

    issue(0);
    issue(1);
    for (int s = 0; s < 16; s++) {
        if (s < 14) CP_WAIT(1);
        else        CP_WAIT(0);
        __syncthreads();
        if (s + 2 < 16) issue(s + 2);
        const uint32_t sb = smb + (s % 3) * GST;
        #pragma unroll
        for (int ks = 0; ks < 4; ks++) {
            uint32_t ah[4][4];
            #pragma unroll
            for (int mt = 0; mt < 4; mt++) {
                uint32_t ad = sb + (uint32_t)((wm * 64 + mt * 16 + (l & 15)) * 144
                                              + ks * 32 + (l >> 4) * 16);
                ldsm4(ah[mt][0], ah[mt][1], ah[mt][2], ah[mt][3], ad);
            }
            uint32_t bh[4][2];
            #pragma unroll
            for (int jj = 0; jj < 2; jj++) {
                uint32_t bd = sb + GSTA
                    + (uint32_t)((ks * 16 + (l & 7) + ((l >> 3) & 1) * 8) * 272
                                 + wn * 64 + jj * 32 + ((l >> 4) & 1) * 16);
                uint32_t r0, r1, r2, r3;
                ldsm4t(r0, r1, r2, r3, bd);
                bh[2*jj][0] = r0; bh[2*jj][1] = r1;
                bh[2*jj+1][0] = r2; bh[2*jj+1][1] = r3;
            }
            #pragma unroll
            for (int mt = 0; mt < 4; mt++)
                #pragma unroll
                for (int nt = 0; nt < 4; nt++)
                    mma16816(acc[mt][nt], ah[mt], bh[nt][0], bh[nt][1]);
        }
    }

    #pragma unroll
    for (int mt = 0; mt < 4; mt++) {
        const int rA = m0 + wm * 64 + mt * 16 + (l >> 2);
        const int rB = rA + 8;
        #pragma unroll
        for (int nt = 0; nt < 4; nt++) {
            const int n = n0 + wn * 32 + nt * 8 + 2 * (l & 3);
            const float bi0 = bias[n], bi1 = bias[n + 1];
            float v0 = acc[mt][nt][0] + bi0, v1 = acc[mt][nt][1] + bi1;
            float v2 = acc[mt][nt][2] + bi0, v3 = acc[mt][nt][3] + bi1;
            if (EPI == 0) {
                const int which = n >> 10;
                const int h = (n & 1023) >> 6, d = n & 63;
                const int bA = rA >> 11, tA = rA & 2047;
                const int bB = rB >> 11, tB = rB & 2047;
                const size_t oA = (((size_t)(bA * NH + h)) * TT + tA) * HD + d;
                const size_t oB = (((size_t)(bB * NH + h)) * TT + tB) * HD + d;
                if (which == 0) {
                    hi_store(g_qh, oA, v0 * QSCALE, v1 * QSCALE);
                    hi_store(g_qh, oB, v2 * QSCALE, v3 * QSCALE);
                } else if (which == 1) {
                    hi_store(g_kh, oA, v0, v1);
                    hi_store(g_kh, oB, v2, v3);
                } else {
                    hi_store(g_vh, oA, v0, v1);
                    hi_store(g_vh, oB, v2, v3);
                }
            } else {
                *(float2*)&outp[(size_t)rA * CC + n] = make_float2(v0, v1);
                *(float2*)&outp[(size_t)rB * CC + n] = make_float2(v2, v3);
            }
        }
    }
}

// ---------------------------------------------------------------------------
// Flash attention: 128 thr / 4 warps, 2 m-frags/warp, 128-row q tile,
// 64-col KV, NOW 3 stages + occupancy 3 (12 warps/SM).
// Q fragments are reloaded from smem per ks (frees 32 persistent regs so the
// kernel fits the 170-reg cap of launch_bounds(128,3)).
// base-2 f16x2-ex2 softmax, l via ones-column mma (V pad holds {1.0h,0...}).
// smem: Qh@0 (18432) | 3 KV stages @18432 + stg*18432 (Kh, Vh@+9216) = 73728
// ---------------------------------------------------------------------------
#define FKV_OFF 18432
#define FKV_ST 18432
#define FLASH_SMEM (FKV_OFF + 3*FKV_ST)   // 73728; x3 CTA = 221184

__global__ __launch_bounds__(128, 3) void flash_mma()
{
    extern __shared__ char smc[];
    const uint32_t smb = smem_u32(smc);
    const int t = threadIdx.x, w = t >> 5, l = t & 31;
    const int qt = (int)gridDim.x - 1 - (int)blockIdx.x;   // heavy tiles first
    const int h = blockIdx.y, b = blockIdx.z;
    const size_t hoff = ((size_t)(b * NH + h)) * TT * HD;
    const int q0 = qt * 128;
    const int nk = 2 * qt + 2;

    auto kvload = [&](int kt) {
        const uint32_t sb = smb + FKV_OFF + (kt % 3) * FKV_ST;
        const int k0 = kt * 64;
        #pragma unroll
        for (int i = 0; i < 4; i++) {
            int c = t + i * 128, row = c >> 3, q = c & 7;
            uint32_t so = (uint32_t)(row * 144 + q * 16);
            size_t g = hoff + (size_t)(k0 + row) * HD + q * 8;
            cpasync16(sb + so,        g_kh + g);
            cpasync16(sb + 9216 + so, g_vh + g);
        }
        CP_COMMIT();
    };

    // Ones-column init: V padding bytes [128,144) of every row, all 3 stages.
    for (int i = t; i < 192; i += 128) {
        int stg = i >> 6, row = i & 63;
        *(uint4*)(smc + FKV_OFF + stg * FKV_ST + 9216 + row * 144 + 128) =
            make_uint4(0x00003C00u, 0u, 0u, 0u);
    }

    // Q: 128 rows x 8 chunks = 1024; shares commit group with kvload(0)
    #pragma unroll
    for (int i = 0; i < 8; i++) {
        int c = t + i * 128, row = c >> 3, q = c & 7;
        uint32_t so = (uint32_t)(row * 144 + q * 16);
        cpasync16(smb + so, g_qh + hoff + (size_t)(q0 + row) * HD + q * 8);
    }
    kvload(0);
    if (1 < nk) kvload(1);

    float mr[2][2];
    float o[2][8][4];
    float o_l[2][4];
    #pragma unroll
    for (int mt = 0; mt < 2; mt++) {
        mr[mt][0] = -1e30f; mr[mt][1] = -1e30f;
        #pragma unroll
        for (int j = 0; j < 8; j++)
            #pragma unroll
            for (int k = 0; k < 4; k++) o[mt][j][k] = 0.f;
        #pragma unroll
        for (int k = 0; k < 4; k++) o_l[mt][k] = 0.f;
    }

    for (int kt = 0; kt < nk; kt++) {
        if (kt + 2 < nk) CP_WAIT(1);
        else             CP_WAIT(0);
        __syncthreads();
        if (kt + 2 < nk) kvload(kt + 2);
        const uint32_t sb = smb + FKV_OFF + (kt % 3) * FKV_ST;

        // S = Q K^T  (Q fragments reloaded per ks; K frags feed both m-frags)
        float s[2][8][4];
        #pragma unroll
        for (int mt = 0; mt < 2; mt++)
            #pragma unroll
            for (int j = 0; j < 8; j++)
                #pragma unroll
                for (int k = 0; k < 4; k++) s[mt][j][k] = 0.f;
        #pragma unroll
        for (int ks = 0; ks < 4; ks++) {
            uint32_t qh[2][4];
            #pragma unroll
            for (int mt = 0; mt < 2; mt++) {
                uint32_t ad = smb + (uint32_t)((w * 32 + mt * 16 + (l & 15)) * 144
                                               + ks * 32 + (l >> 4) * 16);
                ldsm4(qh[mt][0], qh[mt][1], qh[mt][2], qh[mt][3], ad);
            }
            #pragma unroll
            for (int j = 0; j < 4; j++) {
                uint32_t kd = sb + (uint32_t)((16 * j + (l & 7) + ((l >> 4) & 1) * 8) * 144
                                              + ks * 32 + ((l >> 3) & 1) * 16);
                uint32_t r0, r1, r2, r3;
                ldsm4(r0, r1, r2, r3, kd);
                #pragma unroll
                for (int mt = 0; mt < 2; mt++) {
                    mma16816(s[mt][2*j],   qh[mt], r0, r1);
                    mma16816(s[mt][2*j+1], qh[mt], r2, r3);
                }
            }
        }

        if (kt >= 2 * qt) {
            const int cb = 2 * (l & 3);
            #pragma unroll
            for (int mt = 0; mt < 2; mt++) {
                const int rA = q0 + w * 32 + mt * 16 + (l >> 2), rB = rA + 8;
                #pragma unroll
                for (int j = 0; j < 8; j++) {
                    int cg = kt * 64 + 8 * j + cb;
                    if (cg     > rA) s[mt][j][0] = -1e30f;
                    if (cg + 1 > rA) s[mt][j][1] = -1e30f;
                    if (cg     > rB) s[mt][j][2] = -1e30f;
                    if (cg + 1 > rB) s[mt][j][3] = -1e30f;
                }
            }
        }

        // online softmax (base-2, per m-frag), pack P to fp16
        uint32_t ph[2][8][2];
        #pragma unroll
        for (int mt = 0; mt < 2; mt++) {
            float mxA = -1e30f, mxB = -1e30f;
            #pragma unroll
            for (int j = 0; j < 8; j++) {
                mxA = fmaxf(mxA, fmaxf(s[mt][j][0], s[mt][j][1]));
                mxB = fmaxf(mxB, fmaxf(s[mt][j][2], s[mt][j][3]));
            }
            mxA = fmaxf(mxA, __shfl_xor_sync(0xffffffffu, mxA, 1));
            mxA = fmaxf(mxA, __shfl_xor_sync(0xffffffffu, mxA, 2));
            mxB = fmaxf(mxB, __shfl_xor_sync(0xffffffffu, mxB, 1));
            mxB = fmaxf(mxB, __shfl_xor_sync(0xffffffffu, mxB, 2));
            const float nmA = fmaxf(mr[mt][0], mxA), nmB = fmaxf(mr[mt][1], mxB);
            const float aA = exp2f(mr[mt][0] - nmA), aB = exp2f(mr[mt][1] - nmB);
            mr[mt][0] = nmA; mr[mt][1] = nmB;
            #pragma unroll
            for (int j = 0; j < 8; j++) {
                ph[mt][j][0] = h2ex2(pack_h2(s[mt][j][0] - nmA, s[mt][j][1] - nmA));
                ph[mt][j][1] = h2ex2(pack_h2(s[mt][j][2] - nmB, s[mt][j][3] - nmB));
            }
            #pragma unroll
            for (int j = 0; j < 8; j++) {
                o[mt][j][0] *= aA; o[mt][j][1] *= aA;
                o[mt][j][2] *= aB; o[mt][j][3] *= aB;
            }
            o_l[mt][0] *= aA; o_l[mt][1] *= aA;
            o_l[mt][2] *= aB; o_l[mt][3] *= aB;
        }

        // O += P V ; l += P * ones  (V fragments feed both m-frags)
        #pragma unroll
        for (int ks = 0; ks < 4; ks++) {
            uint32_t pa[2][4];
            #pragma unroll
            for (int mt = 0; mt < 2; mt++) {
                pa[mt][0] = ph[mt][2*ks][0];   pa[mt][1] = ph[mt][2*ks][1];
                pa[mt][2] = ph[mt][2*ks+1][0]; pa[mt][3] = ph[mt][2*ks+1][1];
            }
            #pragma unroll
            for (int j = 0; j < 4; j++) {
                uint32_t vd = sb + 9216
                    + (uint32_t)((ks * 16 + (l & 7) + ((l >> 3) & 1) * 8) * 144
                                 + 32 * j + ((l >> 4) & 1) * 16);
                uint32_t r0, r1, r2, r3;
                ldsm4t(r0, r1, r2, r3, vd);
                #pragma unroll
                for (int mt = 0; mt < 2; mt++) {
                    mma16816(o[mt][2*j],   pa[mt], r0, r1);
                    mma16816(o[mt][2*j+1], pa[mt], r2, r3);
                }
            }
            uint32_t v0, v1;
            ldsm2t(v0, v1, sb + 9216
                   + (uint32_t)((ks * 16 + (l & 7) + ((l >> 3) & 1) * 8) * 144 + 128));
            #pragma unroll
            for (int mt = 0; mt < 2; mt++)
                mma16816(o_l[mt], pa[mt], v0, v1);
        }
    }

    // l lives at quad-base lane of o_l[mt][0] (row A) / o_l[mt][2] (row B)
    const int qb = l & ~3;
    #pragma unroll
    for (int mt = 0; mt < 2; mt++) {
        const float lA = __shfl_sync(0xffffffffu, o_l[mt][0], qb);
        const float lB = __shfl_sync(0xffffffffu, o_l[mt][2], qb);
        const float iA = 1.f / lA, iB = 1.f / lB;
        const int rA = q0 + w * 32 + mt * 16 + (l >> 2), rB = rA + 8;
        const size_t baseA = ((size_t)(b * TT + rA)) * CC + h * HD;
        const size_t baseB = ((size_t)(b * TT + rB)) * CC + h * HD;
        #pragma unroll
        for (int j = 0; j < 8; j++) {
            const int d = 8 * j + 2 * (l & 3);
            hi_store(g_ah, baseA + d, o[mt][j][0] * iA, o[mt][j][1] * iA);
            hi_store(g_ah, baseB + d, o[mt][j][2] * iB, o[mt][j][3] * iB);
        }
    }
}

// ---------------------------------------------------------------------------
extern "C" void kernel_launch(void* const* d_in, const int* in_sizes, int n_in,
                              void* d_out, int out_size)
{
    const float* x      = (const float*)d_in[0];
    const float* w_attn = (const float*)d_in[1];
    const float* b_attn = (const float*)d_in[2];
    const float* w_proj = (const float*)d_in[3];
    const float* b_proj = (const float*)d_in[4];
    float* out = (float*)d_out;

    cudaFuncSetAttribute(mma_gemm<0>, cudaFuncAttributeMaxDynamicSharedMemorySize, GSMEM);
    cudaFuncSetAttribute(mma_gemm<1>, cudaFuncAttributeMaxDynamicSharedMemorySize, GSMEM);
    cudaFuncSetAttribute(flash_mma, cudaFuncAttributeMaxDynamicSharedMemorySize, FLASH_SMEM);

    prep_convert<<<PREP_BLOCKS, 256>>>(x, w_attn, w_proj);
    mma_gemm<0><<<dim3(N_QKV / 128, M1 / 128), 256, GSMEM>>>(b_attn, nullptr);
    flash_mma<<<dim3(TT / 128, NH, BB), 128, FLASH_SMEM>>>();
    mma_gemm<1><<<dim3(CC / 128, M1 / 128), 256, GSMEM>>>(b_proj, out);
}

// round 15
// speedup vs baseline: 1.0252x; 1.0252x over previous
#include <cuda_runtime.h>
#include <cuda_fp16.h>
#include <cstdint>
#include <math.h>

#define BB 4
#define TT 2048
#define CC 1024
#define NH 16
#define HD 64
#define M1 (BB*TT)          // 8192
#define N_QKV (3*CC)        // 3072

// q pre-scale: 1/sqrt(64) * log2(e)  -> softmax computed base-2
#define QSCALE 0.180336880111120436f

// ---------------------------------------------------------------------------
// Device-global scratch: pure fp16 operands.  Weights kept K-major [K,N].
// ---------------------------------------------------------------------------
__device__ __half g_xh[M1*CC];
__device__ __half g_wq[CC*N_QKV];     // [K=1024, N=3072] fp16
__device__ __half g_wp[CC*CC];        // [K=1024, N=1024] fp16
__device__ __half g_qh[BB*NH*TT*HD];
__device__ __half g_kh[BB*NH*TT*HD];
__device__ __half g_vh[BB*NH*TT*HD];
__device__ __half g_ah[M1*CC];

// ---------------------------------------------------------------------------
// PTX helpers
// ---------------------------------------------------------------------------
__device__ __forceinline__ uint32_t smem_u32(const void* p) {
    uint32_t a;
    asm("{ .reg .u64 t; cvta.to.shared.u64 t, %1; cvt.u32.u64 %0, t; }"
        : "=r"(a) : "l"(p));
    return a;
}
__device__ __forceinline__ void cpasync16(uint32_t dst, const void* src) {
    asm volatile("cp.async.cg.shared.global [%0], [%1], 16;"
                 :: "r"(dst), "l"(src) : "memory");
}
#define CP_COMMIT() asm volatile("cp.async.commit_group;" ::: "memory")
#define CP_WAIT(N)  asm volatile("cp.async.wait_group %0;" :: "n"(N) : "memory")

__device__ __forceinline__ void ldsm4(uint32_t& r0, uint32_t& r1, uint32_t& r2,
                                      uint32_t& r3, uint32_t a) {
    asm volatile("ldmatrix.sync.aligned.m8n8.x4.shared.b16 {%0,%1,%2,%3},[%4];"
                 : "=r"(r0), "=r"(r1), "=r"(r2), "=r"(r3) : "r"(a));
}
__device__ __forceinline__ void ldsm4t(uint32_t& r0, uint32_t& r1, uint32_t& r2,
                                       uint32_t& r3, uint32_t a) {
    asm volatile("ldmatrix.sync.aligned.m8n8.x4.trans.shared.b16 {%0,%1,%2,%3},[%4];"
                 : "=r"(r0), "=r"(r1), "=r"(r2), "=r"(r3) : "r"(a));
}
__device__ __forceinline__ void ldsm2t(uint32_t& r0, uint32_t& r1, uint32_t a) {
    asm volatile("ldmatrix.sync.aligned.m8n8.x2.trans.shared.b16 {%0,%1},[%2];"
                 : "=r"(r0), "=r"(r1) : "r"(a));
}
__device__ __forceinline__ void mma16816(float* c, const uint32_t* a,
                                         uint32_t b0, uint32_t b1) {
    asm volatile("mma.sync.aligned.m16n8k16.row.col.f32.f16.f16.f32 "
                 "{%0,%1,%2,%3},{%4,%5,%6,%7},{%8,%9},{%0,%1,%2,%3};"
                 : "+f"(c[0]), "+f"(c[1]), "+f"(c[2]), "+f"(c[3])
                 : "r"(a[0]), "r"(a[1]), "r"(a[2]), "r"(a[3]), "r"(b0), "r"(b1));
}

__device__ __forceinline__ void hi_store(__half* dh, size_t off, float v0, float v1) {
    __half2 hp = __halves2half2(__float2half(v0), __float2half(v1));
    *(uint32_t*)(dh + off) = *(uint32_t*)&hp;
}
__device__ __forceinline__ uint32_t pack_h2(float v0, float v1) {
    __half2 hp = __halves2half2(__float2half(v0), __float2half(v1));
    return *(uint32_t*)&hp;
}
__device__ __forceinline__ uint32_t h2ex2(uint32_t x) {
    uint32_t r;
    asm volatile("ex2.approx.f16x2 %0, %1;" : "=r"(r) : "r"(x));
    return r;
}

// ---------------------------------------------------------------------------
// Fused prep: x, w_attn, w_proj fp32 -> fp16 (coalesced, 8B stores)
// ---------------------------------------------------------------------------
#define N_X4  (M1*CC/4)          // 2097152
#define N_WQ4 (CC*N_QKV/4)       // 786432
#define N_WP4 (CC*CC/4)          // 262144
#define PREP_BLOCKS ((N_X4 + N_WQ4 + N_WP4) / 256)   // 12288

__global__ __launch_bounds__(256) void prep_convert(const float* __restrict__ x,
                                                    const float* __restrict__ wa,
                                                    const float* __restrict__ wp)
{
    int i = blockIdx.x * 256 + threadIdx.x;
    const float* src;
    __half* dst;
    if (i < N_X4)               { src = x;  dst = g_xh; }
    else if (i < N_X4 + N_WQ4)  { i -= N_X4;  src = wa; dst = g_wq; }
    else                        { i -= N_X4 + N_WQ4; src = wp; dst = g_wp; }
    float4 v = ((const float4*)src)[i];
    uint2 p;
    p.x = pack_h2(v.x, v.y);
    p.y = pack_h2(v.z, v.w);
    *(uint2*)(dst + (size_t)i * 4) = p;
}

// ---------------------------------------------------------------------------
// GEMM (R11-exact, best measured): C[128x128] = A[M,1024] @ W[1024,N] + bias.
// 256 thr, 8 warps (2x4) 64x32 tiles, BK=64, 3 stages.
// A smem: 128 rows x 144B (ldsm4). B smem: 64 k-rows x 272B (ldsm4t).
// ---------------------------------------------------------------------------
#define GSTA 18432
#define GSTB 17408
#define GST  (GSTA + GSTB)       // 35840
#define GSMEM (3*GST)            // 107520

template<int EPI>
__global__ __launch_bounds__(256, 2) void mma_gemm(const float* __restrict__ bias,
                                                   float* __restrict__ outp)
{
    const __half* Ah = (EPI == 0) ? g_xh : g_ah;
    const __half* Bw = (EPI == 0) ? g_wq : g_wp;
    const int N = (EPI == 0) ? N_QKV : CC;

    extern __shared__ char smc[];
    const uint32_t smb = smem_u32(smc);
    const int t = threadIdx.x, wid = t >> 5, l = t & 31;
    const int wm = wid >> 2, wn = wid & 3;
    const int n0 = blockIdx.x * 128, m0 = blockIdx.y * 128;

    float acc[4][4][4];
    #pragma unroll
    for (int i = 0; i < 4; i++)
        #pragma unroll
        for (int j = 0; j < 4; j++)
            #pragma unroll
            for (int k = 0; k < 4; k++) acc[i][j][k] = 0.f;

    auto issue = [&](int s) {
        const int koff = s * 64;
        const uint32_t sb = smb + (s % 3) * GST;
        #pragma unroll
        for (int i = 0; i < 4; i++) {
            int c = t + i * 256;
            int row = c >> 3, q = c & 7;
            cpasync16(sb + (uint32_t)(row * 144 + q * 16),
                      Ah + (size_t)(m0 + row) * CC + koff + q * 8);
        }
        #pragma unroll
        for (int i = 0; i < 4; i++) {
            int c = t + i * 256;
            int row = c >> 4, q = c & 15;
            cpasync16(sb + GSTA + (uint32_t)(row * 272 + q * 16),
                      Bw + (size_t)(koff + row) * N + n0 + q * 8);
        }
        CP_COMMIT();
    };

    issue(0);
    issue(1);
    for (int s = 0; s < 16; s++) {
        if (s < 14) CP_WAIT(1);
        else        CP_WAIT(0);
        __syncthreads();
        if (s + 2 < 16) issue(s + 2);
        const uint32_t sb = smb + (s % 3) * GST;
        #pragma unroll
        for (int ks = 0; ks < 4; ks++) {
            uint32_t ah[4][4];
            #pragma unroll
            for (int mt = 0; mt < 4; mt++) {
                uint32_t ad = sb + (uint32_t)((wm * 64 + mt * 16 + (l & 15)) * 144
                                              + ks * 32 + (l >> 4) * 16);
                ldsm4(ah[mt][0], ah[mt][1], ah[mt][2], ah[mt][3], ad);
            }
            uint32_t bh[4][2];
            #pragma unroll
            for (int jj = 0; jj < 2; jj++) {
                uint32_t bd = sb + GSTA
                    + (uint32_t)((ks * 16 + (l & 7) + ((l >> 3) & 1) * 8) * 272
                                 + wn * 64 + jj * 32 + ((l >> 4) & 1) * 16);
                uint32_t r0, r1, r2, r3;
                ldsm4t(r0, r1, r2, r3, bd);
                bh[2*jj][0] = r0; bh[2*jj][1] = r1;
                bh[2*jj+1][0] = r2; bh[2*jj+1][1] = r3;
            }
            #pragma unroll
            for (int mt = 0; mt < 4; mt++)
                #pragma unroll
                for (int nt = 0; nt < 4; nt++)
                    mma16816(acc[mt][nt], ah[mt], bh[nt][0], bh[nt][1]);
        }
    }

    #pragma unroll
    for (int mt = 0; mt < 4; mt++) {
        const int rA = m0 + wm * 64 + mt * 16 + (l >> 2);
        const int rB = rA + 8;
        #pragma unroll
        for (int nt = 0; nt < 4; nt++) {
            const int n = n0 + wn * 32 + nt * 8 + 2 * (l & 3);
            const float bi0 = bias[n], bi1 = bias[n + 1];
            float v0 = acc[mt][nt][0] + bi0, v1 = acc[mt][nt][1] + bi1;
            float v2 = acc[mt][nt][2] + bi0, v3 = acc[mt][nt][3] + bi1;
            if (EPI == 0) {
                const int which = n >> 10;
                const int h = (n & 1023) >> 6, d = n & 63;
                const int bA = rA >> 11, tA = rA & 2047;
                const int bB = rB >> 11, tB = rB & 2047;
                const size_t oA = (((size_t)(bA * NH + h)) * TT + tA) * HD + d;
                const size_t oB = (((size_t)(bB * NH + h)) * TT + tB) * HD + d;
                if (which == 0) {
                    hi_store(g_qh, oA, v0 * QSCALE, v1 * QSCALE);
                    hi_store(g_qh, oB, v2 * QSCALE, v3 * QSCALE);
                } else if (which == 1) {
                    hi_store(g_kh, oA, v0, v1);
                    hi_store(g_kh, oB, v2, v3);
                } else {
                    hi_store(g_vh, oA, v0, v1);
                    hi_store(g_vh, oB, v2, v3);
                }
            } else {
                *(float2*)&outp[(size_t)rA * CC + n] = make_float2(v0, v1);
                *(float2*)&outp[(size_t)rB * CC + n] = make_float2(v2, v3);
            }
        }
    }
}

// ---------------------------------------------------------------------------
// Flash attention (R11-exact, best measured): 128 thr / 4 warps,
// 2 m-frags/warp (persistent Q fragments), 128-row q tile, 64-col KV,
// 4 stages, occupancy 2, base-2 f16x2-ex2 softmax, l via ones-column mma.
// smem: Qh@0 (18432) | 4 KV stages @18432 + stg*18432 (Kh, Vh@+9216) = 92160
// ---------------------------------------------------------------------------
#define FKV_OFF 18432
#define FKV_ST 18432
#define FLASH_SMEM (FKV_OFF + 4*FKV_ST)   // 92160

__global__ __launch_bounds__(128, 2) void flash_mma()
{
    extern __shared__ char smc[];
    const uint32_t smb = smem_u32(smc);
    const int t = threadIdx.x, w = t >> 5, l = t & 31;
    const int qt = (int)gridDim.x - 1 - (int)blockIdx.x;   // heavy tiles first
    const int h = blockIdx.y, b = blockIdx.z;
    const size_t hoff = ((size_t)(b * NH + h)) * TT * HD;
    const int q0 = qt * 128;
    const int nk = 2 * qt + 2;

    auto kvload = [&](int kt) {
        const uint32_t sb = smb + FKV_OFF + (kt & 3) * FKV_ST;
        const int k0 = kt * 64;
        #pragma unroll
        for (int i = 0; i < 4; i++) {
            int c = t + i * 128, row = c >> 3, q = c & 7;
            uint32_t so = (uint32_t)(row * 144 + q * 16);
            size_t g = hoff + (size_t)(k0 + row) * HD + q * 8;
            cpasync16(sb + so,        g_kh + g);
            cpasync16(sb + 9216 + so, g_vh + g);
        }
        CP_COMMIT();
    };

    // Ones-column init: V padding bytes [128,144) of every row, all 4 stages.
    for (int i = t; i < 256; i += 128) {
        int stg = i >> 6, row = i & 63;
        *(uint4*)(smc + FKV_OFF + stg * FKV_ST + 9216 + row * 144 + 128) =
            make_uint4(0x00003C00u, 0u, 0u, 0u);
    }

    // Q: 128 rows x 8 chunks = 1024; shares commit group with kvload(0)
    #pragma unroll
    for (int i = 0; i < 8; i++) {
        int c = t + i * 128, row = c >> 3, q = c & 7;
        uint32_t so = (uint32_t)(row * 144 + q * 16);
        cpasync16(smb + so, g_qh + hoff + (size_t)(q0 + row) * HD + q * 8);
    }
    kvload(0);
    if (1 < nk) kvload(1);
    if (2 < nk) kvload(2);

    float mr[2][2];
    float o[2][8][4];
    float o_l[2][4];
    #pragma unroll
    for (int mt = 0; mt < 2; mt++) {
        mr[mt][0] = -1e30f; mr[mt][1] = -1e30f;
        #pragma unroll
        for (int j = 0; j < 8; j++)
            #pragma unroll
            for (int k = 0; k < 4; k++) o[mt][j][k] = 0.f;
        #pragma unroll
        for (int k = 0; k < 4; k++) o_l[mt][k] = 0.f;
    }

    uint32_t qh[2][4][4];

    for (int kt = 0; kt < nk; kt++) {
        if (kt + 3 < nk) CP_WAIT(2);
        else             CP_WAIT(0);
        __syncthreads();
        if (kt + 3 < nk) kvload(kt + 3);
        if (kt == 0) {
            #pragma unroll
            for (int mt = 0; mt < 2; mt++)
                #pragma unroll
                for (int ks = 0; ks < 4; ks++) {
                    uint32_t ad = smb + (uint32_t)((w * 32 + mt * 16 + (l & 15)) * 144
                                                   + ks * 32 + (l >> 4) * 16);
                    ldsm4(qh[mt][ks][0], qh[mt][ks][1], qh[mt][ks][2], qh[mt][ks][3], ad);
                }
        }
        const uint32_t sb = smb + FKV_OFF + (kt & 3) * FKV_ST;

        // S = Q K^T  (K fragments feed both m-frags)
        float s[2][8][4];
        #pragma unroll
        for (int mt = 0; mt < 2; mt++)
            #pragma unroll
            for (int j = 0; j < 8; j++)
                #pragma unroll
                for (int k = 0; k < 4; k++) s[mt][j][k] = 0.f;
        #pragma unroll
        for (int ks = 0; ks < 4; ks++) {
            #pragma unroll
            for (int j = 0; j < 4; j++) {
                uint32_t kd = sb + (uint32_t)((16 * j + (l & 7) + ((l >> 4) & 1) * 8) * 144
                                              + ks * 32 + ((l >> 3) & 1) * 16);
                uint32_t r0, r1, r2, r3;
                ldsm4(r0, r1, r2, r3, kd);
                #pragma unroll
                for (int mt = 0; mt < 2; mt++) {
                    mma16816(s[mt][2*j],   qh[mt][ks], r0, r1);
                    mma16816(s[mt][2*j+1], qh[mt][ks], r2, r3);
                }
            }
        }

        if (kt >= 2 * qt) {
            const int cb = 2 * (l & 3);
            #pragma unroll
            for (int mt = 0; mt < 2; mt++) {
                const int rA = q0 + w * 32 + mt * 16 + (l >> 2), rB = rA + 8;
                #pragma unroll
                for (int j = 0; j < 8; j++) {
                    int cg = kt * 64 + 8 * j + cb;
                    if (cg     > rA) s[mt][j][0] = -1e30f;
                    if (cg + 1 > rA) s[mt][j][1] = -1e30f;
                    if (cg     > rB) s[mt][j][2] = -1e30f;
                    if (cg + 1 > rB) s[mt][j][3] = -1e30f;
                }
            }
        }

        // online softmax (base-2, per m-frag), pack P to fp16
        uint32_t ph[2][8][2];
        #pragma unroll
        for (int mt = 0; mt < 2; mt++) {
            float mxA = -1e30f, mxB = -1e30f;
            #pragma unroll
            for (int j = 0; j < 8; j++) {
                mxA = fmaxf(mxA, fmaxf(s[mt][j][0], s[mt][j][1]));
                mxB = fmaxf(mxB, fmaxf(s[mt][j][2], s[mt][j][3]));
            }
            mxA = fmaxf(mxA, __shfl_xor_sync(0xffffffffu, mxA, 1));
            mxA = fmaxf(mxA, __shfl_xor_sync(0xffffffffu, mxA, 2));
            mxB = fmaxf(mxB, __shfl_xor_sync(0xffffffffu, mxB, 1));
            mxB = fmaxf(mxB, __shfl_xor_sync(0xffffffffu, mxB, 2));
            const float nmA = fmaxf(mr[mt][0], mxA), nmB = fmaxf(mr[mt][1], mxB);
            const float aA = exp2f(mr[mt][0] - nmA), aB = exp2f(mr[mt][1] - nmB);
            mr[mt][0] = nmA; mr[mt][1] = nmB;
            #pragma unroll
            for (int j = 0; j < 8; j++) {
                ph[mt][j][0] = h2ex2(pack_h2(s[mt][j][0] - nmA, s[mt][j][1] - nmA));
                ph[mt][j][1] = h2ex2(pack_h2(s[mt][j][2] - nmB, s[mt][j][3] - nmB));
            }
            #pragma unroll
            for (int j = 0; j < 8; j++) {
                o[mt][j][0] *= aA; o[mt][j][1] *= aA;
                o[mt][j][2] *= aB; o[mt][j][3] *= aB;
            }
            o_l[mt][0] *= aA; o_l[mt][1] *= aA;
            o_l[mt][2] *= aB; o_l[mt][3] *= aB;
        }

        // O += P V ; l += P * ones  (V fragments feed both m-frags)
        #pragma unroll
        for (int ks = 0; ks < 4; ks++) {
            uint32_t pa[2][4];
            #pragma unroll
            for (int mt = 0; mt < 2; mt++) {
                pa[mt][0] = ph[mt][2*ks][0];   pa[mt][1] = ph[mt][2*ks][1];
                pa[mt][2] = ph[mt][2*ks+1][0]; pa[mt][3] = ph[mt][2*ks+1][1];
            }
            #pragma unroll
            for (int j = 0; j < 4; j++) {
                uint32_t vd = sb + 9216
                    + (uint32_t)((ks * 16 + (l & 7) + ((l >> 3) & 1) * 8) * 144
                                 + 32 * j + ((l >> 4) & 1) * 16);
                uint32_t r0, r1, r2, r3;
                ldsm4t(r0, r1, r2, r3, vd);
                #pragma unroll
                for (int mt = 0; mt < 2; mt++) {
                    mma16816(o[mt][2*j],   pa[mt], r0, r1);
                    mma16816(o[mt][2*j+1], pa[mt], r2, r3);
                }
            }
            uint32_t v0, v1;
            ldsm2t(v0, v1, sb + 9216
                   + (uint32_t)((ks * 16 + (l & 7) + ((l >> 3) & 1) * 8) * 144 + 128));
            #pragma unroll
            for (int mt = 0; mt < 2; mt++)
                mma16816(o_l[mt], pa[mt], v0, v1);
        }
    }

    // l lives at quad-base lane of o_l[mt][0] (row A) / o_l[mt][2] (row B)
    const int qb = l & ~3;
    #pragma unroll
    for (int mt = 0; mt < 2; mt++) {
        const float lA = __shfl_sync(0xffffffffu, o_l[mt][0], qb);
        const float lB = __shfl_sync(0xffffffffu, o_l[mt][2], qb);
        const float iA = 1.f / lA, iB = 1.f / lB;
        const int rA = q0 + w * 32 + mt * 16 + (l >> 2), rB = rA + 8;
        const size_t baseA = ((size_t)(b * TT + rA)) * CC + h * HD;
        const size_t baseB = ((size_t)(b * TT + rB)) * CC + h * HD;
        #pragma unroll
        for (int j = 0; j < 8; j++) {
            const int d = 8 * j + 2 * (l & 3);
            hi_store(g_ah, baseA + d, o[mt][j][0] * iA, o[mt][j][1] * iA);
            hi_store(g_ah, baseB + d, o[mt][j][2] * iB, o[mt][j][3] * iB);
        }
    }
}

// ---------------------------------------------------------------------------
extern "C" void kernel_launch(void* const* d_in, const int* in_sizes, int n_in,
                              void* d_out, int out_size)
{
    const float* x      = (const float*)d_in[0];
    const float* w_attn = (const float*)d_in[1];
    const float* b_attn = (const float*)d_in[2];
    const float* w_proj = (const float*)d_in[3];
    const float* b_proj = (const float*)d_in[4];
    float* out = (float*)d_out;

    cudaFuncSetAttribute(mma_gemm<0>, cudaFuncAttributeMaxDynamicSharedMemorySize, GSMEM);
    cudaFuncSetAttribute(mma_gemm<1>, cudaFuncAttributeMaxDynamicSharedMemorySize, GSMEM);
    cudaFuncSetAttribute(flash_mma, cudaFuncAttributeMaxDynamicSharedMemorySize, FLASH_SMEM);

    prep_convert<<<PREP_BLOCKS, 256>>>(x, w_attn, w_proj);
    mma_gemm<0><<<dim3(N_QKV / 128, M1 / 128), 256, GSMEM>>>(b_attn, nullptr);
    flash_mma<<<dim3(TT / 128, NH, BB), 128, FLASH_SMEM>>>();
    mma_gemm<1><<<dim3(CC / 128, M1 / 128), 256, GSMEM>>>(b_proj, out);
}

// round 16
// speedup vs baseline: 1.0310x; 1.0057x over previous
#include <cuda_runtime.h>
#include <cuda_fp16.h>
#include <cstdint>
#include <math.h>

#define BB 4
#define TT 2048
#define CC 1024
#define NH 16
#define HD 64
#define M1 (BB*TT)          // 8192
#define N_QKV (3*CC)        // 3072

// q pre-scale: 1/sqrt(64) * log2(e)  -> softmax computed base-2
#define QSCALE 0.180336880111120436f

// ---------------------------------------------------------------------------
// Device-global scratch: pure fp16 operands.  Weights kept K-major [K,N].
// ---------------------------------------------------------------------------
__device__ __half g_xh[M1*CC];
__device__ __half g_wq[CC*N_QKV];     // [K=1024, N=3072] fp16
__device__ __half g_wp[CC*CC];        // [K=1024, N=1024] fp16
__device__ __half g_qh[BB*NH*TT*HD];
__device__ __half g_kh[BB*NH*TT*HD];
__device__ __half g_vh[BB*NH*TT*HD];
__device__ __half g_ah[M1*CC];

// ---------------------------------------------------------------------------
// PTX helpers
// ---------------------------------------------------------------------------
__device__ __forceinline__ uint32_t smem_u32(const void* p) {
    uint32_t a;
    asm("{ .reg .u64 t; cvta.to.shared.u64 t, %1; cvt.u32.u64 %0, t; }"
        : "=r"(a) : "l"(p));
    return a;
}
__device__ __forceinline__ void cpasync16(uint32_t dst, const void* src) {
    asm volatile("cp.async.cg.shared.global [%0], [%1], 16;"
                 :: "r"(dst), "l"(src) : "memory");
}
#define CP_COMMIT() asm volatile("cp.async.commit_group;" ::: "memory")
#define CP_WAIT(N)  asm volatile("cp.async.wait_group %0;" :: "n"(N) : "memory")

__device__ __forceinline__ void ldsm4(uint32_t& r0, uint32_t& r1, uint32_t& r2,
                                      uint32_t& r3, uint32_t a) {
    asm volatile("ldmatrix.sync.aligned.m8n8.x4.shared.b16 {%0,%1,%2,%3},[%4];"
                 : "=r"(r0), "=r"(r1), "=r"(r2), "=r"(r3) : "r"(a));
}
__device__ __forceinline__ void ldsm4t(uint32_t& r0, uint32_t& r1, uint32_t& r2,
                                       uint32_t& r3, uint32_t a) {
    asm volatile("ldmatrix.sync.aligned.m8n8.x4.trans.shared.b16 {%0,%1,%2,%3},[%4];"
                 : "=r"(r0), "=r"(r1), "=r"(r2), "=r"(r3) : "r"(a));
}
__device__ __forceinline__ void mma16816(float* c, const uint32_t* a,
                                         uint32_t b0, uint32_t b1) {
    asm volatile("mma.sync.aligned.m16n8k16.row.col.f32.f16.f16.f32 "
                 "{%0,%1,%2,%3},{%4,%5,%6,%7},{%8,%9},{%0,%1,%2,%3};"
                 : "+f"(c[0]), "+f"(c[1]), "+f"(c[2]), "+f"(c[3])
                 : "r"(a[0]), "r"(a[1]), "r"(a[2]), "r"(a[3]), "r"(b0), "r"(b1));
}

__device__ __forceinline__ void hi_store(__half* dh, size_t off, float v0, float v1) {
    __half2 hp = __halves2half2(__float2half(v0), __float2half(v1));
    *(uint32_t*)(dh + off) = *(uint32_t*)&hp;
}
__device__ __forceinline__ uint32_t pack_h2(float v0, float v1) {
    __half2 hp = __halves2half2(__float2half(v0), __float2half(v1));
    return *(uint32_t*)&hp;
}
__device__ __forceinline__ uint32_t h2ex2(uint32_t x) {
    uint32_t r;
    asm volatile("ex2.approx.f16x2 %0, %1;" : "=r"(r) : "r"(x));
    return r;
}

// ---------------------------------------------------------------------------
// Fused prep: x, w_attn, w_proj fp32 -> fp16 (coalesced, 8B stores)
// ---------------------------------------------------------------------------
#define N_X4  (M1*CC/4)          // 2097152
#define N_WQ4 (CC*N_QKV/4)       // 786432
#define N_WP4 (CC*CC/4)          // 262144
#define PREP_BLOCKS ((N_X4 + N_WQ4 + N_WP4) / 256)   // 12288

__global__ __launch_bounds__(256) void prep_convert(const float* __restrict__ x,
                                                    const float* __restrict__ wa,
                                                    const float* __restrict__ wp)
{
    int i = blockIdx.x * 256 + threadIdx.x;
    const float* src;
    __half* dst;
    if (i < N_X4)               { src = x;  dst = g_xh; }
    else if (i < N_X4 + N_WQ4)  { i -= N_X4;  src = wa; dst = g_wq; }
    else                        { i -= N_X4 + N_WQ4; src = wp; dst = g_wp; }
    float4 v = ((const float4*)src)[i];
    uint2 p;
    p.x = pack_h2(v.x, v.y);
    p.y = pack_h2(v.z, v.w);
    *(uint2*)(dst + (size_t)i * 4) = p;
}

// ---------------------------------------------------------------------------
// GEMM (R11 base): C[128x128] = A[M,1024] @ W[1024,N] + bias.
// 256 thr, 8 warps (2x4) 64x32 tiles, BK=64, 3 stages.
// A smem: 128 rows x 144B (ldsm4). B smem: 64 k-rows x 272B (ldsm4t).
// CP_WAIT ladder exact: wait(1) while a group remains prefetched (s<15).
// ---------------------------------------------------------------------------
#define GSTA 18432
#define GSTB 17408
#define GST  (GSTA + GSTB)       // 35840
#define GSMEM (3*GST)            // 107520

template<int EPI>
__global__ __launch_bounds__(256, 2) void mma_gemm(const float* __restrict__ bias,
                                                   float* __restrict__ outp)
{
    const __half* Ah = (EPI == 0) ? g_xh : g_ah;
    const __half* Bw = (EPI == 0) ? g_wq : g_wp;
    const int N = (EPI == 0) ? N_QKV : CC;

    extern __shared__ char smc[];
    const uint32_t smb = smem_u32(smc);
    const int t = threadIdx.x, wid = t >> 5, l = t & 31;
    const int wm = wid >> 2, wn = wid & 3;
    const int n0 = blockIdx.x * 128, m0 = blockIdx.y * 128;

    float acc[4][4][4];
    #pragma unroll
    for (int i = 0; i < 4; i++)
        #pragma unroll
        for (int j = 0; j < 4; j++)
            #pragma unroll
            for (int k = 0; k < 4; k++) acc[i][j][k] = 0.f;

    auto issue = [&](int s) {
        const int koff = s * 64;
        const uint32_t sb = smb + (s % 3) * GST;
        #pragma unroll
        for (int i = 0; i < 4; i++) {
            int c = t + i * 256;
            int row = c >> 3, q = c & 7;
            cpasync16(sb + (uint32_t)(row * 144 + q * 16),
                      Ah + (size_t)(m0 + row) * CC + koff + q * 8);
        }
        #pragma unroll
        for (int i = 0; i < 4; i++) {
            int c = t + i * 256;
            int row = c >> 4, q = c & 15;
            cpasync16(sb + GSTA + (uint32_t)(row * 272 + q * 16),
                      Bw + (size_t)(koff + row) * N + n0 + q * 8);
        }
        CP_COMMIT();
    };

    issue(0);
    issue(1);
    for (int s = 0; s < 16; s++) {
        if (s < 15) CP_WAIT(1);
        else        CP_WAIT(0);
        __syncthreads();
        if (s + 2 < 16) issue(s + 2);
        const uint32_t sb = smb + (s % 3) * GST;
        #pragma unroll
        for (int ks = 0; ks < 4; ks++) {
            uint32_t ah[4][4];
            #pragma unroll
            for (int mt = 0; mt < 4; mt++) {
                uint32_t ad = sb + (uint32_t)((wm * 64 + mt * 16 + (l & 15)) * 144
                                              + ks * 32 + (l >> 4) * 16);
                ldsm4(ah[mt][0], ah[mt][1], ah[mt][2], ah[mt][3], ad);
            }
            uint32_t bh[4][2];
            #pragma unroll
            for (int jj = 0; jj < 2; jj++) {
                uint32_t bd = sb + GSTA
                    + (uint32_t)((ks * 16 + (l & 7) + ((l >> 3) & 1) * 8) * 272
                                 + wn * 64 + jj * 32 + ((l >> 4) & 1) * 16);
                uint32_t r0, r1, r2, r3;
                ldsm4t(r0, r1, r2, r3, bd);
                bh[2*jj][0] = r0; bh[2*jj][1] = r1;
                bh[2*jj+1][0] = r2; bh[2*jj+1][1] = r3;
            }
            #pragma unroll
            for (int mt = 0; mt < 4; mt++)
                #pragma unroll
                for (int nt = 0; nt < 4; nt++)
                    mma16816(acc[mt][nt], ah[mt], bh[nt][0], bh[nt][1]);
        }
    }

    #pragma unroll
    for (int mt = 0; mt < 4; mt++) {
        const int rA = m0 + wm * 64 + mt * 16 + (l >> 2);
        const int rB = rA + 8;
        #pragma unroll
        for (int nt = 0; nt < 4; nt++) {
            const int n = n0 + wn * 32 + nt * 8 + 2 * (l & 3);
            const float bi0 = bias[n], bi1 = bias[n + 1];
            float v0 = acc[mt][nt][0] + bi0, v1 = acc[mt][nt][1] + bi1;
            float v2 = acc[mt][nt][2] + bi0, v3 = acc[mt][nt][3] + bi1;
            if (EPI == 0) {
                const int which = n >> 10;
                const int h = (n & 1023) >> 6, d = n & 63;
                const int bA = rA >> 11, tA = rA & 2047;
                const int bB = rB >> 11, tB = rB & 2047;
                const size_t oA = (((size_t)(bA * NH + h)) * TT + tA) * HD + d;
                const size_t oB = (((size_t)(bB * NH + h)) * TT + tB) * HD + d;
                if (which == 0) {
                    hi_store(g_qh, oA, v0 * QSCALE, v1 * QSCALE);
                    hi_store(g_qh, oB, v2 * QSCALE, v3 * QSCALE);
                } else if (which == 1) {
                    hi_store(g_kh, oA, v0, v1);
                    hi_store(g_kh, oB, v2, v3);
                } else {
                    hi_store(g_vh, oA, v0, v1);
                    hi_store(g_vh, oB, v2, v3);
                }
            } else {
                *(float2*)&outp[(size_t)rA * CC + n] = make_float2(v0, v1);
                *(float2*)&outp[(size_t)rB * CC + n] = make_float2(v2, v3);
            }
        }
    }
}

// ---------------------------------------------------------------------------
// Flash attention (R11 base): 128 thr / 4 warps, 2 m-frags/warp (persistent
// Q), 128-row q tile, 64-col KV, 4 stages, occ 2, base-2 f16x2-ex2 softmax.
// CHANGES vs R11:
//  - l row-sum uses a LANE-CONSTANT ones B-fragment (m16n8k16 B mapping:
//    n = lane/4; ones col is n==0) instead of 4 ldsm2t per tile + pad init.
//  - exact CP_WAIT ladder (2 / 1 / 0) instead of draining the last 3 tiles.
// smem: Qh@0 (18432) | 4 KV stages @18432 + stg*18432 (Kh, Vh@+9216) = 92160
// ---------------------------------------------------------------------------
#define FKV_OFF 18432
#define FKV_ST 18432
#define FLASH_SMEM (FKV_OFF + 4*FKV_ST)   // 92160

__global__ __launch_bounds__(128, 2) void flash_mma()
{
    extern __shared__ char smc[];
    const uint32_t smb = smem_u32(smc);
    const int t = threadIdx.x, w = t >> 5, l = t & 31;
    const int qt = (int)gridDim.x - 1 - (int)blockIdx.x;   // heavy tiles first
    const int h = blockIdx.y, b = blockIdx.z;
    const size_t hoff = ((size_t)(b * NH + h)) * TT * HD;
    const int q0 = qt * 128;
    const int nk = 2 * qt + 2;

    // Constant ones-column B fragment: b0=b1={1.0h,1.0h} iff this lane's
    // fragment column (l/4) is column 0 of the ones matrix.
    const uint32_t vone = (l < 4) ? 0x3C003C00u : 0u;

    auto kvload = [&](int kt) {
        const uint32_t sb = smb + FKV_OFF + (kt & 3) * FKV_ST;
        const int k0 = kt * 64;
        #pragma unroll
        for (int i = 0; i < 4; i++) {
            int c = t + i * 128, row = c >> 3, q = c & 7;
            uint32_t so = (uint32_t)(row * 144 + q * 16);
            size_t g = hoff + (size_t)(k0 + row) * HD + q * 8;
            cpasync16(sb + so,        g_kh + g);
            cpasync16(sb + 9216 + so, g_vh + g);
        }
        CP_COMMIT();
    };

    // Q: 128 rows x 8 chunks = 1024; shares commit group with kvload(0)
    #pragma unroll
    for (int i = 0; i < 8; i++) {
        int c = t + i * 128, row = c >> 3, q = c & 7;
        uint32_t so = (uint32_t)(row * 144 + q * 16);
        cpasync16(smb + so, g_qh + hoff + (size_t)(q0 + row) * HD + q * 8);
    }
    kvload(0);
    if (1 < nk) kvload(1);
    if (2 < nk) kvload(2);

    float mr[2][2];
    float o[2][8][4];
    float o_l[2][4];
    #pragma unroll
    for (int mt = 0; mt < 2; mt++) {
        mr[mt][0] = -1e30f; mr[mt][1] = -1e30f;
        #pragma unroll
        for (int j = 0; j < 8; j++)
            #pragma unroll
            for (int k = 0; k < 4; k++) o[mt][j][k] = 0.f;
        #pragma unroll
        for (int k = 0; k < 4; k++) o_l[mt][k] = 0.f;
    }

    uint32_t qh[2][4][4];

    for (int kt = 0; kt < nk; kt++) {
        if (kt + 3 <= nk)      { if (kt + 3 < nk) CP_WAIT(2); else CP_WAIT(2); }
        if (kt == nk - 2)      CP_WAIT(1);
        else if (kt == nk - 1) CP_WAIT(0);
        __syncthreads();
        if (kt + 3 < nk) kvload(kt + 3);
        if (kt == 0) {
            #pragma unroll
            for (int mt = 0; mt < 2; mt++)
                #pragma unroll
                for (int ks = 0; ks < 4; ks++) {
                    uint32_t ad = smb + (uint32_t)((w * 32 + mt * 16 + (l & 15)) * 144
                                                   + ks * 32 + (l >> 4) * 16);
                    ldsm4(qh[mt][ks][0], qh[mt][ks][1], qh[mt][ks][2], qh[mt][ks][3], ad);
                }
        }
        const uint32_t sb = smb + FKV_OFF + (kt & 3) * FKV_ST;

        // S = Q K^T  (K fragments feed both m-frags)
        float s[2][8][4];
        #pragma unroll
        for (int mt = 0; mt < 2; mt++)
            #pragma unroll
            for (int j = 0; j < 8; j++)
                #pragma unroll
                for (int k = 0; k < 4; k++) s[mt][j][k] = 0.f;
        #pragma unroll
        for (int ks = 0; ks < 4; ks++) {
            #pragma unroll
            for (int j = 0; j < 4; j++) {
                uint32_t kd = sb + (uint32_t)((16 * j + (l & 7) + ((l >> 4) & 1) * 8) * 144
                                              + ks * 32 + ((l >> 3) & 1) * 16);
                uint32_t r0, r1, r2, r3;
                ldsm4(r0, r1, r2, r3, kd);
                #pragma unroll
                for (int mt = 0; mt < 2; mt++) {
                    mma16816(s[mt][2*j],   qh[mt][ks], r0, r1);
                    mma16816(s[mt][2*j+1], qh[mt][ks], r2, r3);
                }
            }
        }

        if (kt >= 2 * qt) {
            const int cb = 2 * (l & 3);
            #pragma unroll
            for (int mt = 0; mt < 2; mt++) {
                const int rA = q0 + w * 32 + mt * 16 + (l >> 2), rB = rA + 8;
                #pragma unroll
                for (int j = 0; j < 8; j++) {
                    int cg = kt * 64 + 8 * j + cb;
                    if (cg     > rA) s[mt][j][0] = -1e30f;
                    if (cg + 1 > rA) s[mt][j][1] = -1e30f;
                    if (cg     > rB) s[mt][j][2] = -1e30f;
                    if (cg + 1 > rB) s[mt][j][3] = -1e30f;
                }
            }
        }

        // online softmax (base-2, per m-frag), pack P to fp16
        uint32_t ph[2][8][2];
        #pragma unroll
        for (int mt = 0; mt < 2; mt++) {
            float mxA = -1e30f, mxB = -1e30f;
            #pragma unroll
            for (int j = 0; j < 8; j++) {
                mxA = fmaxf(mxA, fmaxf(s[mt][j][0], s[mt][j][1]));
                mxB = fmaxf(mxB, fmaxf(s[mt][j][2], s[mt][j][3]));
            }
            mxA = fmaxf(mxA, __shfl_xor_sync(0xffffffffu, mxA, 1));
            mxA = fmaxf(mxA, __shfl_xor_sync(0xffffffffu, mxA, 2));
            mxB = fmaxf(mxB, __shfl_xor_sync(0xffffffffu, mxB, 1));
            mxB = fmaxf(mxB, __shfl_xor_sync(0xffffffffu, mxB, 2));
            const float nmA = fmaxf(mr[mt][0], mxA), nmB = fmaxf(mr[mt][1], mxB);
            const float aA = exp2f(mr[mt][0] - nmA), aB = exp2f(mr[mt][1] - nmB);
            mr[mt][0] = nmA; mr[mt][1] = nmB;
            #pragma unroll
            for (int j = 0; j < 8; j++) {
                ph[mt][j][0] = h2ex2(pack_h2(s[mt][j][0] - nmA, s[mt][j][1] - nmA));
                ph[mt][j][1] = h2ex2(pack_h2(s[mt][j][2] - nmB, s[mt][j][3] - nmB));
            }
            #pragma unroll
            for (int j = 0; j < 8; j++) {
                o[mt][j][0] *= aA; o[mt][j][1] *= aA;
                o[mt][j][2] *= aB; o[mt][j][3] *= aB;
            }
            o_l[mt][0] *= aA; o_l[mt][1] *= aA;
            o_l[mt][2] *= aB; o_l[mt][3] *= aB;
        }

        // O += P V ; l += P * ones  (V fragments feed both m-frags;
        // ones B-frag is the lane constant vone)
        #pragma unroll
        for (int ks = 0; ks < 4; ks++) {
            uint32_t pa[2][4];
            #pragma unroll
            for (int mt = 0; mt < 2; mt++) {
                pa[mt][0] = ph[mt][2*ks][0];   pa[mt][1] = ph[mt][2*ks][1];
                pa[mt][2] = ph[mt][2*ks+1][0]; pa[mt][3] = ph[mt][2*ks+1][1];
            }
            #pragma unroll
            for (int j = 0; j < 4; j++) {
                uint32_t vd = sb + 9216
                    + (uint32_t)((ks * 16 + (l & 7) + ((l >> 3) & 1) * 8) * 144
                                 + 32 * j + ((l >> 4) & 1) * 16);
                uint32_t r0, r1, r2, r3;
                ldsm4t(r0, r1, r2, r3, vd);
                #pragma unroll
                for (int mt = 0; mt < 2; mt++) {
                    mma16816(o[mt][2*j],   pa[mt], r0, r1);
                    mma16816(o[mt][2*j+1], pa[mt], r2, r3);
                }
            }
            #pragma unroll
            for (int mt = 0; mt < 2; mt++)
                mma16816(o_l[mt], pa[mt], vone, vone);
        }
    }

    // l lives at quad-base lane of o_l[mt][0] (row A) / o_l[mt][2] (row B)
    const int qb = l & ~3;
    #pragma unroll
    for (int mt = 0; mt < 2; mt++) {
        const float lA = __shfl_sync(0xffffffffu, o_l[mt][0], qb);
        const float lB = __shfl_sync(0xffffffffu, o_l[mt][2], qb);
        const float iA = 1.f / lA, iB = 1.f / lB;
        const int rA = q0 + w * 32 + mt * 16 + (l >> 2), rB = rA + 8;
        const size_t baseA = ((size_t)(b * TT + rA)) * CC + h * HD;
        const size_t baseB = ((size_t)(b * TT + rB)) * CC + h * HD;
        #pragma unroll
        for (int j = 0; j < 8; j++) {
            const int d = 8 * j + 2 * (l & 3);
            hi_store(g_ah, baseA + d, o[mt][j][0] * iA, o[mt][j][1] * iA);
            hi_store(g_ah, baseB + d, o[mt][j][2] * iB, o[mt][j][3] * iB);
        }
    }
}

// ---------------------------------------------------------------------------
extern "C" void kernel_launch(void* const* d_in, const int* in_sizes, int n_in,
                              void* d_out, int out_size)
{
    const float* x      = (const float*)d_in[0];
    const float* w_attn = (const float*)d_in[1];
    const float* b_attn = (const float*)d_in[2];
    const float* w_proj = (const float*)d_in[3];
    const float* b_proj = (const float*)d_in[4];
    float* out = (float*)d_out;

    cudaFuncSetAttribute(mma_gemm<0>, cudaFuncAttributeMaxDynamicSharedMemorySize, GSMEM);
    cudaFuncSetAttribute(mma_gemm<1>, cudaFuncAttributeMaxDynamicSharedMemorySize, GSMEM);
    cudaFuncSetAttribute(flash_mma, cudaFuncAttributeMaxDynamicSharedMemorySize, FLASH_SMEM);

    prep_convert<<<PREP_BLOCKS, 256>>>(x, w_attn, w_proj);
    mma_gemm<0><<<dim3(N_QKV / 128, M1 / 128), 256, GSMEM>>>(b_attn, nullptr);
    flash_mma<<<dim3(TT / 128, NH, BB), 128, FLASH_SMEM>>>();
    mma_gemm<1><<<dim3(CC / 128, M1 / 128), 256, GSMEM>>>(b_proj, out);
}